// round 16
// baseline (speedup 1.0000x reference)
#include <cuda_runtime.h>
#include <cstdint>

// Fixed problem shapes
static constexpr int NP     = 128;           // partitions
static constexpr int Cc     = 32;            // key channels
static constexpr int Dd     = 128;           // value/query dim
static constexpr int Bb     = 4;
static constexpr int Ss     = 2048;
static constexpr int Kk     = 2;
static constexpr int NPAIRS = Bb * Ss * Kk;  // 16384
static constexpr int NTOK   = Bb * Ss;       // 8192

static constexpr int NTHR   = 1024;
static constexpr int NBLK   = 2 * NP;        // 256 blocks = (partition, half)
static constexpr int HALFN  = NPAIRS / 2;    // 8192 pairs per half
static constexpr int PER    = HALFN / 4 / NTHR;    // 2 int4 per thread
static constexpr int CAP    = 512;           // per-(p,half) capacity (mean 64, sigma 8)

static constexpr int ONTHR  = 256;
static constexpr int ONBLK  = 512;                     // 512 blocks
static constexpr int OSTR   = ONBLK * ONTHR;           // 131072; 2 f4/thread

// Persistent scratch: per-(half,partition) partial rows. Fully rewritten by
// k_scatter every launch (gather formulation -> no zeroing, no atomics).
__device__ float g_P[2 * NP * Dd];

// ---------------------------------------------------------------------------
// k_scatter: 256 blocks x 1024 threads, 2 CTAs/SM. Block (p,h):
//   Phase 1:   scan half h of idx (2 int4/thread, strided-coalesced),
//              two-level shfl scan -> deterministic compaction (~64 matches).
//   Phase 1.5: w[m] = mean_c keys[j_m,:], 8 threads/row octet-shfl.
//   Phase 2:   float4 gather thread=(slice,d4); transpose + warp-shfl
//              reduce -> g_P[h][p] row.
// ---------------------------------------------------------------------------
__global__ void __launch_bounds__(NTHR, 2) k_scatter(
    const int*   __restrict__ idx,
    const float* __restrict__ keys,
    const float* __restrict__ values)
{
    __shared__ int    js[CAP];
    __shared__ float  wls[CAP];
    __shared__ int    wsum[32];
    __shared__ float4 red4[32][33];          // padded transpose buffer

    const int p    = blockIdx.x >> 1;
    const int h    = blockIdx.x & 1;
    const int tid  = threadIdx.x;
    const int lane = tid & 31;
    const int wid  = tid >> 5;

    // ---- Phase 1a: strided-coalesced idx load (2 int4/thread), count
    const int4* idx4 = (const int4*)idx + h * (HALFN / 4);
    int4 my[PER];
    int cnt = 0;
    #pragma unroll
    for (int i = 0; i < PER; i++) {
        my[i] = idx4[i * NTHR + tid];
        cnt += (my[i].x == p) + (my[i].y == p) + (my[i].z == p) + (my[i].w == p);
    }

    // ---- Phase 1b: two-level exclusive scan (warp shfl + 32-entry top)
    int inc = cnt;
    #pragma unroll
    for (int o = 1; o < 32; o <<= 1) {
        int v = __shfl_up_sync(0xFFFFFFFFu, inc, o);
        if (lane >= o) inc += v;
    }
    if (lane == 31) wsum[wid] = inc;
    __syncthreads();
    if (wid == 0) {
        int v = wsum[lane];
        #pragma unroll
        for (int o = 1; o < 32; o <<= 1) {
            int u = __shfl_up_sync(0xFFFFFFFFu, v, o);
            if (lane >= o) v += u;
        }
        wsum[lane] = v;                      // inclusive prefix of warp totals
    }
    __syncthreads();
    int n   = wsum[31];
    int pos = (wid ? wsum[wid - 1] : 0) + (inc - cnt);

    // ---- Phase 1c: emit matched pair indices (fixed deterministic order)
    #pragma unroll
    for (int i = 0; i < PER; i++) {
        const int j = h * HALFN + (i * NTHR + tid) * 4;
        if (my[i].x == p && pos < CAP) js[pos++] = j + 0;
        if (my[i].y == p && pos < CAP) js[pos++] = j + 1;
        if (my[i].z == p && pos < CAP) js[pos++] = j + 2;
        if (my[i].w == p && pos < CAP) js[pos++] = j + 3;
    }
    if (n > CAP) n = CAP;
    __syncthreads();

    // ---- Phase 1.5: weights, 8 threads per 128B key row, octet shfl.
    {
        const int lane8 = tid & 7;
        const int row8  = tid >> 3;
        for (int b = 0; b < n; b += NTHR / 8) {
            const int m = b + row8;
            float s = 0.f;
            if (m < n) {
                float4 v = ((const float4*)keys)[(size_t)js[m] * (Cc / 4) + lane8];
                s = (v.x + v.y) + (v.z + v.w);
            }
            s += __shfl_xor_sync(0xFFFFFFFFu, s, 1);
            s += __shfl_xor_sync(0xFFFFFFFFu, s, 2);
            s += __shfl_xor_sync(0xFFFFFFFFu, s, 4);
            if (m < n && lane8 == 0) wls[m] = s * (1.0f / Cc);
        }
    }
    __syncthreads();

    // ---- Phase 2: float4 gather, thread=(slice,d4); ~2 matches/thread.
    {
        const int slice = tid >> 5;
        const int d4    = tid & 31;
        const float4* V4 = (const float4*)values;
        float4 acc = make_float4(0.f, 0.f, 0.f, 0.f);
        for (int m = slice; m < n; m += 32) {
            const float w = wls[m];
            float4 v = V4[(js[m] >> 1) * 32 + d4];
            acc.x += w * v.x; acc.y += w * v.y;
            acc.z += w * v.z; acc.w += w * v.w;
        }
        red4[slice][d4] = acc;
        __syncthreads();
        // warp-transpose reduce: warp `wid` owns column d4=wid, lanes=slices
        float4 v = red4[lane][wid];
        #pragma unroll
        for (int o = 16; o >= 1; o >>= 1) {
            v.x += __shfl_down_sync(0xFFFFFFFFu, v.x, o);
            v.y += __shfl_down_sync(0xFFFFFFFFu, v.y, o);
            v.z += __shfl_down_sync(0xFFFFFFFFu, v.z, o);
            v.w += __shfl_down_sync(0xFFFFFFFFu, v.w, o);
        }
        if (lane == 0)
            ((float4*)g_P)[(h * NP + p) * 32 + wid] = v;
    }
}

// ---------------------------------------------------------------------------
// k_out: 512 blocks x 256 threads, 2 float4 per thread. All independent
// loads (q x2, idx x2) issue first, then all 8 P gathers, then compute +
// 2 stores — maximal per-thread bytes in flight, half the blocks to ramp.
// ---------------------------------------------------------------------------
__global__ void __launch_bounds__(ONTHR) k_out(
    const int*   __restrict__ idx,
    const float* __restrict__ q,
    float*       __restrict__ out)
{
    const int i0 = blockIdx.x * ONTHR + threadIdx.x;   // first f4 index
    const int i1 = i0 + OSTR;                          // second f4 index

    // Independent DRAM loads first
    const float4 q0 = __ldg((const float4*)q + i0);
    const float4 q1 = __ldg((const float4*)q + i1);
    const int2   a  = __ldg((const int2*)idx + (i0 >> 5));
    const int2   b  = __ldg((const int2*)idx + (i1 >> 5));

    const int d40 = i0 & 31;
    const int d41 = i1 & 31;
    const float4* P0 = (const float4*)g_P;             // half-0 rows
    const float4* P1 = P0 + NP * (Dd / 4);             // half-1 rows

    // All 8 P gathers issued back-to-back (L2-resident rows)
    float4 a0 = P0[a.x * 32 + d40];
    float4 a1 = P1[a.x * 32 + d40];
    float4 a2 = P0[a.y * 32 + d40];
    float4 a3 = P1[a.y * 32 + d40];
    float4 b0 = P0[b.x * 32 + d41];
    float4 b1 = P1[b.x * 32 + d41];
    float4 b2 = P0[b.y * 32 + d41];
    float4 b3 = P1[b.y * 32 + d41];

    float4 o0, o1;
    o0.x = ((a0.x + a1.x) + (a2.x + a3.x)) * q0.x;
    o0.y = ((a0.y + a1.y) + (a2.y + a3.y)) * q0.y;
    o0.z = ((a0.z + a1.z) + (a2.z + a3.z)) * q0.z;
    o0.w = ((a0.w + a1.w) + (a2.w + a3.w)) * q0.w;
    o1.x = ((b0.x + b1.x) + (b2.x + b3.x)) * q1.x;
    o1.y = ((b0.y + b1.y) + (b2.y + b3.y)) * q1.y;
    o1.z = ((b0.z + b1.z) + (b2.z + b3.z)) * q1.z;
    o1.w = ((b0.w + b1.w) + (b2.w + b3.w)) * q1.w;
    ((float4*)out)[i0] = o0;
    ((float4*)out)[i1] = o1;
}

extern "C" void kernel_launch(void* const* d_in, const int* in_sizes, int n_in,
                              void* d_out, int out_size)
{
    const int*   idx     = (const int*)  d_in[0];  // [B,S,K] int32
    const float* keys    = (const float*)d_in[1];  // [B,S,K,C] f32
    const float* values  = (const float*)d_in[2];  // [B,S,D]   f32
    const float* queries = (const float*)d_in[3];  // [B,S,D]   f32
    float*       out     = (float*)d_out;          // [B,S,D]   f32

    (void)in_sizes; (void)n_in; (void)out_size;

    k_scatter<<<NBLK, NTHR>>>(idx, keys, values);
    k_out<<<ONBLK, ONTHR>>>(idx, queries, out);
}